// round 16
// baseline (speedup 1.0000x reference)
#include <cuda_runtime.h>
#include <cuda_bf16.h>
#include <cstdint>

// ---------------- constants ----------------
constexpr int kNCTA = 1024;        // 8192 samples / 8 per CTA (M = 128)
constexpr int kNT   = 512;         // 16 warps, warp tile 32m x 32n
constexpr int XS    = 42;          // x0 fp32 row stride (floats)
constexpr int XB2   = 22;          // x0 bf16x2 row stride (u32)
constexpr int H2S   = 36;          // hidden row stride (u32 bf16x2)

constexpr int NCH0  = 14;          // layer 0: 210 triu groups + pad
constexpr int NG0   = 210;
constexpr int NCH12 = 39;

constexpr int B_OFF  = 0;                        // 2 x 16384 B buffers
constexpr int XF_OFF = 32768;                    // x0 fp32: 128*42*4 = 21504
constexpr int XB_OFF = XF_OFF + 128 * XS * 4;    // x0 bf16x2: 128*22*4 = 11264
constexpr int H_OFF  = XB_OFF + 128 * XB2 * 4;   // hidden: 128*36*4 = 18432
constexpr int W_OFF  = H_OFF + 128 * H2S * 4;    // wf: 256 fp32
constexpr int RA_OFF = W_OFF + 256 * 4;          // rowacc: 128 x 4 fp32
constexpr int S_OFF  = RA_OFF + 512 * 4;         // score: 8 fp32
constexpr int T_OFF  = S_OFF + 64;               // layer-0 table: 224 ints
constexpr int SMEM_ALLOC = T_OFF + 224 * 4;      // ~88 KB, 1 CTA/SM (RF-bound)

// ---------------- device scratch ----------------
// per chunk: 2 kp-blocks x 16 ntiles x 32 lanes x uint4 = 1024 uint4 (16 KB)
__device__ __align__(16) uint2 g_Wt0[NCH0 * 2048];
__device__ __align__(16) uint2 g_Wt1[NCH12 * 2048];
__device__ __align__(16) uint2 g_Wt2[NCH12 * 2048];
__device__ int g_L0map[224];       // (i << 8) | j0 per group g

// ---------------- helpers ----------------
__device__ __forceinline__ uint32_t smem_u32(const void* p) {
    uint32_t a;
    asm("{ .reg .u64 t; cvta.to.shared.u64 t, %1; cvt.u32.u64 %0, t; }" : "=r"(a) : "l"(p));
    return a;
}
__device__ __forceinline__ uint32_t packbf(float lo, float hi) {
    uint32_t r;
    asm("cvt.rn.bf16x2.f32 %0, %1, %2;" : "=r"(r) : "f"(hi), "f"(lo));
    return r;
}
__device__ __forceinline__ uint32_t mulbf2(uint32_t a, uint32_t b) {
    uint32_t r;
    asm("mul.bf16x2 %0, %1, %2;" : "=r"(r) : "r"(a), "r"(b));
    return r;
}
__device__ __forceinline__ void mma16816(float* c, const uint32_t* a, uint32_t b0, uint32_t b1) {
    asm volatile(
        "mma.sync.aligned.m16n8k16.row.col.f32.bf16.bf16.f32 "
        "{%0,%1,%2,%3}, {%4,%5,%6,%7}, {%8,%9}, {%0,%1,%2,%3};"
        : "+f"(c[0]), "+f"(c[1]), "+f"(c[2]), "+f"(c[3])
        : "r"(a[0]), "r"(a[1]), "r"(a[2]), "r"(a[3]), "r"(b0), "r"(b1));
}
__device__ __forceinline__ void cp16(uint32_t d, const void* s) {
    asm volatile("cp.async.ca.shared.global [%0], [%1], 16;" :: "r"(d), "l"(s) : "memory");
}
#define CP_COMMIT() asm volatile("cp.async.commit_group;" ::: "memory")
#define CP_WAIT(n)  asm volatile("cp.async.wait_group %0;" :: "n"(n) : "memory")

__device__ __forceinline__ void prefetch_chunk(const uint2* Wt, int c, int buf,
                                               uint32_t sb, int tid) {
    const char* src = (const char*)(Wt + (size_t)c * 2048);
    uint32_t dst = sb + B_OFF + buf * 16384;
#pragma unroll
    for (int v = 0; v < 2; ++v)
        cp16(dst + (v * 512 + tid) * 16, src + (v * 512 + tid) * 16);
    CP_COMMIT();
}

// ---------------- layer-0 group table ----------------
__global__ void cin_l0map() {
    if (threadIdx.x == 0) {
        int g = 0;
        for (int i = 0; i < 39; ++i)
            for (int j0 = 0; j0 < 39; j0 += 4)
                if (j0 + 3 > i) g_L0map[g++] = (i << 8) | j0;
        for (; g < 224; ++g) g_L0map[g] = 0;
    }
}

// ---------------- weight prep (layout unchanged from R8) ----------------
__global__ void cin_wprep(const float* __restrict__ f, uint2* __restrict__ wt,
                          int which, int nch) {
    int e = blockIdx.x * 256 + threadIdx.x;
    if (e >= nch * 2048) return;
    int c = e >> 11, rem = e & 2047;
    int w = rem & 1, s2 = rem >> 1;
    int lane = s2 & 31, nt = (s2 >> 5) & 15, kp = s2 >> 9;
    int ks = kp * 2 + w;
    int n = nt * 8 + (lane >> 2), tq = lane & 3;
    float v[4];
    if (which == 0) {
        int g = c * 16 + ks * 4 + tq;
        int ent = g_L0map[g];
        int i = ent >> 8, j0 = ent & 255;
#pragma unroll
        for (int t = 0; t < 4; ++t) {
            int j = j0 + t;
            float x = 0.0f;
            if (g < NG0 && j < 39 && j > i) x = 2.0f * f[(size_t)(39 * i + j) * 128 + n];
            v[t] = x;
        }
    } else {
        int k0 = c * 64 + ks * 16 + tq * 2;
        v[0] = f[(size_t)k0 * 128 + n];
        v[1] = f[(size_t)(k0 + 1) * 128 + n];
        v[2] = f[(size_t)(k0 + 8) * 128 + n];
        v[3] = f[(size_t)(k0 + 9) * 128 + n];
    }
    wt[e] = make_uint2(packbf(v[0], v[1]), packbf(v[2], v[3]));
}

// ---------------- per-layer body ----------------
template <int LAYER>
__device__ __forceinline__ void run_layer(char* smem, uint32_t sb, const uint2* Wt) {
    const int tid  = threadIdx.x;
    const int lane = tid & 31, wid = tid >> 5;
    const int m0 = (wid >> 2) * 32;           // 4 m-groups
    const int wn = wid & 3;                   // 4 n-groups
    const int nt0 = wn * 4, n0 = wn * 32;
    const int q = lane >> 2, tq = lane & 3;

    float*    x0f   = (float*)(smem + XF_OFF);
    uint32_t* x0b   = (uint32_t*)(smem + XB_OFF);
    uint32_t* hsf2  = (uint32_t*)(smem + H_OFF);
    float*    wf    = (float*)(smem + W_OFF);
    float*    ra    = (float*)(smem + RA_OFF);
    float*    score = (float*)(smem + S_OFF);
    const int* tab  = (const int*)(smem + T_OFF);

    int ru[4];
#pragma unroll
    for (int u = 0; u < 4; ++u) ru[u] = m0 + q + u * 8;   // {mt0:r, mt0:r+8, mt1:r, mt1:r+8}

    // hidden operand in registers for the whole layer (layers 1-2)
    uint32_t hreg[4][8];
    if (LAYER > 0) {
#pragma unroll
        for (int u = 0; u < 4; ++u)
#pragma unroll
            for (int t = 0; t < 8; ++t)
                hreg[u][t] = hsf2[ru[u] * H2S + tq + 4 * t];
    }

    constexpr int NCH = (LAYER == 0) ? NCH0 : NCH12;
    float acc[2][4][4];
#pragma unroll
    for (int mt = 0; mt < 2; ++mt)
#pragma unroll
        for (int nt = 0; nt < 4; ++nt)
#pragma unroll
            for (int j = 0; j < 4; ++j) acc[mt][nt][j] = 0.0f;

    prefetch_chunk(Wt, 0, 0, sb, tid);

    for (int c = 0; c < NCH; ++c) {
        int buf = c & 1;
        if (c + 1 < NCH) { prefetch_chunk(Wt, c + 1, buf ^ 1, sb, tid); CP_WAIT(1); }
        else            { CP_WAIT(0); }
        __syncthreads();

        const uint4* Bc = (const uint4*)(smem + B_OFF + buf * 16384);

        uint32_t xi2[4];
        if (LAYER > 0) {
#pragma unroll
            for (int u = 0; u < 4; ++u) { float x = x0f[ru[u] * XS + c]; xi2[u] = packbf(x, x); }
        }

#pragma unroll
        for (int kp = 0; kp < 2; ++kp) {
            uint32_t afr0[2][4], afr1[2][4];
#pragma unroll
            for (int h = 0; h < 2; ++h) {                  // ks = 2*kp + h
                int ks = 2 * kp + h;
                uint32_t (*afr)[4] = h ? afr1 : afr0;
                if (LAYER == 0) {
                    int ent = tab[c * 16 + ks * 4 + tq];
                    int i = ent >> 8, j0 = ent & 255;
                    uint32_t pa[4], pb[4];
#pragma unroll
                    for (int u = 0; u < 4; ++u) {
                        float xf = x0f[ru[u] * XS + i];
                        uint32_t xb = packbf(xf, xf);
                        uint2 hx = *(const uint2*)(x0b + ru[u] * XB2 + (j0 >> 1));
                        pa[u] = mulbf2(xb, hx.x);          // cols j0, j0+1
                        pb[u] = mulbf2(xb, hx.y);          // cols j0+2, j0+3
                    }
#pragma unroll
                    for (int mt = 0; mt < 2; ++mt) {
                        afr[mt][0] = pa[2 * mt];  afr[mt][1] = pa[2 * mt + 1];
                        afr[mt][2] = pb[2 * mt];  afr[mt][3] = pb[2 * mt + 1];
                    }
                } else {
#pragma unroll
                    for (int mt = 0; mt < 2; ++mt) {
                        afr[mt][0] = mulbf2(xi2[2 * mt],     hreg[2 * mt][2 * ks]);
                        afr[mt][1] = mulbf2(xi2[2 * mt + 1], hreg[2 * mt + 1][2 * ks]);
                        afr[mt][2] = mulbf2(xi2[2 * mt],     hreg[2 * mt][2 * ks + 1]);
                        afr[mt][3] = mulbf2(xi2[2 * mt + 1], hreg[2 * mt + 1][2 * ks + 1]);
                    }
                }
            }
#pragma unroll
            for (int nt = 0; nt < 4; ++nt) {
                uint4 b = Bc[(kp * 16 + nt0 + nt) * 32 + lane];
                mma16816(acc[0][nt], afr0[0], b.x, b.y);
                mma16816(acc[1][nt], afr0[1], b.x, b.y);
                mma16816(acc[0][nt], afr1[0], b.z, b.w);
                mma16816(acc[1][nt], afr1[1], b.z, b.w);
            }
        }
        __syncthreads();
    }

    // ---- epilogue: relu, bf16x2 hidden writeback, weighted per-row sums ----
    float rsum[4] = {0.0f, 0.0f, 0.0f, 0.0f};
#pragma unroll
    for (int mt = 0; mt < 2; ++mt) {
        int r = m0 + mt * 16 + q;
#pragma unroll
        for (int nt = 0; nt < 4; ++nt) {
            int c0 = n0 + nt * 8 + tq * 2;
            float v0 = fmaxf(acc[mt][nt][0], 0.0f);
            float v1 = fmaxf(acc[mt][nt][1], 0.0f);
            float v2 = fmaxf(acc[mt][nt][2], 0.0f);
            float v3 = fmaxf(acc[mt][nt][3], 0.0f);
            if (LAYER == 2 || c0 >= 64) {
                int wi = (LAYER == 0) ? (c0 - 64) : (LAYER == 1 ? c0 : 128 + c0);
                float w0 = wf[wi], w1 = wf[wi + 1];
                rsum[mt * 2]     += v0 * w0 + v1 * w1;
                rsum[mt * 2 + 1] += v2 * w0 + v3 * w1;
            } else {  // hidden half (LAYER < 2, wn 0/1): cols c0, c0+1 adjacent
                hsf2[r * H2S + (c0 >> 1)]       = packbf(v0, v1);
                hsf2[(r + 8) * H2S + (c0 >> 1)] = packbf(v2, v3);
            }
        }
    }
#pragma unroll
    for (int m = 1; m <= 2; m <<= 1)
#pragma unroll
        for (int t = 0; t < 4; ++t)
            rsum[t] += __shfl_xor_sync(0xffffffffu, rsum[t], m);
    if (tq == 0) {                                 // 512 unique (row, wn) slots
        ra[(m0 + q) * 4 + wn]      = rsum[0];
        ra[(m0 + q + 8) * 4 + wn]  = rsum[1];
        ra[(m0 + q + 16) * 4 + wn] = rsum[2];
        ra[(m0 + q + 24) * 4 + wn] = rsum[3];
    }
    __syncthreads();

    if (tid < 8) {
        float s = 0.0f;
#pragma unroll
        for (int d = 0; d < 16; ++d) {
            int r = tid * 16 + d;
            s += ra[r * 4] + ra[r * 4 + 1] + ra[r * 4 + 2] + ra[r * 4 + 3];
        }
        score[tid] += s;
    }
    __syncthreads();
}

// ---------------- main kernel ----------------
__global__ __launch_bounds__(kNT, 1)
void cin_main(const float* __restrict__ nn_input, const float* __restrict__ w_nn,
              const float* __restrict__ b_nn, float* __restrict__ out) {
    extern __shared__ __align__(16) char smem[];
    uint32_t sb = smem_u32(smem);
    int tid = threadIdx.x;

    float*    x0f   = (float*)(smem + XF_OFF);
    uint32_t* x0b   = (uint32_t*)(smem + XB_OFF);
    float*    wf    = (float*)(smem + W_OFF);
    float*    score = (float*)(smem + S_OFF);
    int*      tabs  = (int*)(smem + T_OFF);

    int S0 = blockIdx.x * 8;
    for (int idx = tid; idx < 8 * 624; idx += kNT) {
        int s = idx / 624, rem = idx - s * 624;
        int i = rem >> 4, d = rem & 15;
        x0f[(s * 16 + d) * XS + i] = nn_input[(size_t)(S0 + s) * 624 + rem];
    }
    for (int idx = tid; idx < 128 * 3; idx += kNT) {          // pad cols 39..41 = 0
        int r = idx / 3, p = idx - 3 * r;
        x0f[r * XS + 39 + p] = 0.0f;
    }
    if (tid < 224) tabs[tid] = g_L0map[tid];
    if (tid < 256) wf[tid] = 1.0f + w_nn[tid];
    if (tid < 8)   score[tid] = b_nn[0];
    __syncthreads();

    // bf16x2 x0 copy for layer-0 j-pair loads (cols 0..39, col 39 padded 0)
    for (int idx = tid; idx < 128 * 20; idx += kNT) {
        int r = idx / 20, m = idx - r * 20;
        x0b[r * XB2 + m] = packbf(x0f[r * XS + 2 * m], x0f[r * XS + 2 * m + 1]);
    }
    // visibility covered by first chunk's in-loop __syncthreads

    run_layer<0>(smem, sb, g_Wt0);
    run_layer<1>(smem, sb, g_Wt1);
    run_layer<2>(smem, sb, g_Wt2);

    if (tid < 8) out[S0 + tid] = score[tid];
}

// ---------------- launch ----------------
extern "C" void kernel_launch(void* const* d_in, const int* in_sizes, int n_in,
                              void* d_out, int out_size) {
    const float* nn   = (const float*)d_in[0];
    const float* f0   = (const float*)d_in[1];
    const float* f1   = (const float*)d_in[2];
    const float* f2   = (const float*)d_in[3];
    const float* w_nn = (const float*)d_in[4];
    const float* b_nn = (const float*)d_in[5];
    float* out = (float*)d_out;

    cudaFuncSetAttribute(cin_main, cudaFuncAttributeMaxDynamicSharedMemorySize, SMEM_ALLOC);

    uint2* wt0; cudaGetSymbolAddress((void**)&wt0, g_Wt0);
    uint2* wt1; cudaGetSymbolAddress((void**)&wt1, g_Wt1);
    uint2* wt2; cudaGetSymbolAddress((void**)&wt2, g_Wt2);

    cin_l0map<<<1, 32>>>();
    cin_wprep<<<(NCH0  * 2048 + 255) / 256, 256>>>(f0, wt0, 0, NCH0);
    cin_wprep<<<(NCH12 * 2048 + 255) / 256, 256>>>(f1, wt1, 1, NCH12);
    cin_wprep<<<(NCH12 * 2048 + 255) / 256, 256>>>(f2, wt2, 2, NCH12);
    cin_main<<<kNCTA, kNT, SMEM_ALLOC>>>(nn, w_nn, b_nn, out);
}

// round 17
// speedup vs baseline: 1.1369x; 1.1369x over previous
#include <cuda_runtime.h>
#include <cuda_bf16.h>
#include <cstdint>

// ---------------- constants ----------------
constexpr int kNCTA = 1024;        // 8192 samples / 8 per CTA
constexpr int kNT   = 256;         // 8 warps (R8 shape: 4 m-groups x 2 n-groups)
constexpr int XS    = 42;          // x0 fp32 row stride (floats)
constexpr int XB2   = 22;          // x0 bf16x2 row stride (u32)
constexpr int H2S   = 36;          // hidden row stride (u32 bf16x2)

constexpr int NCH0  = 14;          // layer 0: 210 triu groups + pad
constexpr int NG0   = 210;
constexpr int NCH12 = 39;

constexpr int B_OFF  = 0;                        // 2 x 16384 B buffers
constexpr int XF_OFF = 32768;                    // x0 fp32: 128*42*4 = 21504
constexpr int XB_OFF = XF_OFF + 128 * XS * 4;    // x0 bf16x2: 128*22*4 = 11264
constexpr int H_OFF  = XB_OFF + 128 * XB2 * 4;   // hidden: 128*36*4 = 18432
constexpr int W_OFF  = H_OFF + 128 * H2S * 4;    // wf: 256 fp32
constexpr int RA_OFF = W_OFF + 256 * 4;          // rowacc: 128 x 2 fp32
constexpr int S_OFF  = RA_OFF + 256 * 4;         // score: 8 fp32
constexpr int T_OFF  = S_OFF + 64;               // layer-0 table: 224 ints
constexpr int SMEM_ALLOC = T_OFF + 224 * 4;      // ~86.1 KB -> 2 CTAs/SM (172 of 228)

// ---------------- device scratch ----------------
// per chunk: 2 kp-blocks x 16 ntiles x 32 lanes x uint4 = 1024 uint4 (16 KB)
__device__ __align__(16) uint2 g_Wt0[NCH0 * 2048];
__device__ __align__(16) uint2 g_Wt1[NCH12 * 2048];
__device__ __align__(16) uint2 g_Wt2[NCH12 * 2048];
__device__ int g_L0map[224];       // (i << 8) | j0 per group g

// ---------------- helpers ----------------
__device__ __forceinline__ uint32_t smem_u32(const void* p) {
    uint32_t a;
    asm("{ .reg .u64 t; cvta.to.shared.u64 t, %1; cvt.u32.u64 %0, t; }" : "=r"(a) : "l"(p));
    return a;
}
__device__ __forceinline__ uint32_t packbf(float lo, float hi) {
    uint32_t r;
    asm("cvt.rn.bf16x2.f32 %0, %1, %2;" : "=r"(r) : "f"(hi), "f"(lo));
    return r;
}
__device__ __forceinline__ uint32_t mulbf2(uint32_t a, uint32_t b) {
    uint32_t r;
    asm("mul.bf16x2 %0, %1, %2;" : "=r"(r) : "r"(a), "r"(b));
    return r;
}
__device__ __forceinline__ void mma16816(float* c, const uint32_t* a, uint32_t b0, uint32_t b1) {
    asm volatile(
        "mma.sync.aligned.m16n8k16.row.col.f32.bf16.bf16.f32 "
        "{%0,%1,%2,%3}, {%4,%5,%6,%7}, {%8,%9}, {%0,%1,%2,%3};"
        : "+f"(c[0]), "+f"(c[1]), "+f"(c[2]), "+f"(c[3])
        : "r"(a[0]), "r"(a[1]), "r"(a[2]), "r"(a[3]), "r"(b0), "r"(b1));
}
__device__ __forceinline__ void cp16(uint32_t d, const void* s) {
    asm volatile("cp.async.ca.shared.global [%0], [%1], 16;" :: "r"(d), "l"(s) : "memory");
}
#define CP_COMMIT() asm volatile("cp.async.commit_group;" ::: "memory")
#define CP_WAIT(n)  asm volatile("cp.async.wait_group %0;" :: "n"(n) : "memory")

__device__ __forceinline__ void prefetch_chunk(const uint2* Wt, int c, int buf,
                                               uint32_t sb, int tid) {
    const char* src = (const char*)(Wt + (size_t)c * 2048);
    uint32_t dst = sb + B_OFF + buf * 16384;
#pragma unroll
    for (int v = 0; v < 4; ++v)
        cp16(dst + (v * 256 + tid) * 16, src + (v * 256 + tid) * 16);
    CP_COMMIT();
}

// ---------------- layer-0 group table ----------------
// Group g -> (i, j0): j0 4-aligned, group {j0..j0+3} intersects {j : i < j < 39}.
// 210 real groups, pad to 224 with (0,0) (padded weights zeroed in wprep).
__global__ void cin_l0map() {
    if (threadIdx.x == 0) {
        int g = 0;
        for (int i = 0; i < 39; ++i)
            for (int j0 = 0; j0 < 39; j0 += 4)
                if (j0 + 3 > i) g_L0map[g++] = (i << 8) | j0;
        for (; g < 224; ++g) g_L0map[g] = 0;
    }
}

// ---------------- weight prep (layout identical to R8) ----------------
__global__ void cin_wprep(const float* __restrict__ f, uint2* __restrict__ wt,
                          int which, int nch) {
    int e = blockIdx.x * 256 + threadIdx.x;
    if (e >= nch * 2048) return;
    int c = e >> 11, rem = e & 2047;
    int w = rem & 1, s2 = rem >> 1;
    int lane = s2 & 31, nt = (s2 >> 5) & 15, kp = s2 >> 9;
    int ks = kp * 2 + w;
    int n = nt * 8 + (lane >> 2), tq = lane & 3;
    float v[4];
    if (which == 0) {
        int g = c * 16 + ks * 4 + tq;
        int ent = g_L0map[g];
        int i = ent >> 8, j0 = ent & 255;
#pragma unroll
        for (int t = 0; t < 4; ++t) {
            int j = j0 + t;
            float x = 0.0f;
            if (g < NG0 && j < 39 && j > i) x = 2.0f * f[(size_t)(39 * i + j) * 128 + n];
            v[t] = x;
        }
    } else {
        int k0 = c * 64 + ks * 16 + tq * 2;
        v[0] = f[(size_t)k0 * 128 + n];
        v[1] = f[(size_t)(k0 + 1) * 128 + n];
        v[2] = f[(size_t)(k0 + 8) * 128 + n];
        v[3] = f[(size_t)(k0 + 9) * 128 + n];
    }
    wt[e] = make_uint2(packbf(v[0], v[1]), packbf(v[2], v[3]));
}

// ---------------- A-fragment generation ----------------
template <int LAYER>
__device__ __forceinline__ void gen_afr(int ks, int c, int tq,
                                        const float* const* xr,
                                        const uint32_t* const* xb2,
                                        const uint32_t* const* hr2,
                                        const uint32_t* xi2, const int* tab,
                                        uint32_t afr[2][4]) {
    if (LAYER == 0) {
        int ent = tab[c * 16 + ks * 4 + tq];
        int i = ent >> 8, j0 = ent & 255;          // j0 multiple of 4 -> uint2-aligned
        uint32_t pa[4], pb[4];
#pragma unroll
        for (int u = 0; u < 4; ++u) {
            float xf = xr[u][i];
            uint32_t xb = packbf(xf, xf);
            uint2 hx = *(const uint2*)(xb2[u] + (j0 >> 1));
            pa[u] = mulbf2(xb, hx.x);              // cols j0, j0+1
            pb[u] = mulbf2(xb, hx.y);              // cols j0+2, j0+3
        }
#pragma unroll
        for (int mt = 0; mt < 2; ++mt) {
            afr[mt][0] = pa[2 * mt];  afr[mt][1] = pa[2 * mt + 1];
            afr[mt][2] = pb[2 * mt];  afr[mt][3] = pb[2 * mt + 1];
        }
    } else {
        int base = ks * 8 + tq;
#pragma unroll
        for (int mt = 0; mt < 2; ++mt) {
            afr[mt][0] = mulbf2(xi2[2 * mt],     hr2[2 * mt][base]);
            afr[mt][1] = mulbf2(xi2[2 * mt + 1], hr2[2 * mt + 1][base]);
            afr[mt][2] = mulbf2(xi2[2 * mt],     hr2[2 * mt][base + 4]);
            afr[mt][3] = mulbf2(xi2[2 * mt + 1], hr2[2 * mt + 1][base + 4]);
        }
    }
}

// ---------------- per-layer body (R8 structure) ----------------
template <int LAYER>
__device__ __forceinline__ void run_layer(char* smem, uint32_t sb, const uint2* Wt) {
    const int tid  = threadIdx.x;
    const int lane = tid & 31, wid = tid >> 5;
    const int m0 = (wid >> 1) * 32;
    const int wn = wid & 1;
    const int nt0 = wn * 8, n0 = wn * 64;
    const int q = lane >> 2, tq = lane & 3;

    float*    x0f   = (float*)(smem + XF_OFF);
    uint32_t* x0b   = (uint32_t*)(smem + XB_OFF);
    uint32_t* hsf2  = (uint32_t*)(smem + H_OFF);
    float*    wf    = (float*)(smem + W_OFF);
    float*    ra    = (float*)(smem + RA_OFF);
    float*    score = (float*)(smem + S_OFF);
    const int* tab  = (const int*)(smem + T_OFF);

    const float*    xr[4];
    const uint32_t* xb2[4];
    const uint32_t* hr2[4];
#pragma unroll
    for (int u = 0; u < 4; ++u) {
        int r = m0 + q + u * 8;                // u: {mt0:r, mt0:r+8, mt1:r, mt1:r+8}
        xr[u]  = x0f + r * XS;
        xb2[u] = x0b + r * XB2;
        hr2[u] = hsf2 + r * H2S;
    }

    constexpr int NCH = (LAYER == 0) ? NCH0 : NCH12;
    float acc[2][8][4];
#pragma unroll
    for (int mt = 0; mt < 2; ++mt)
#pragma unroll
        for (int nt = 0; nt < 8; ++nt)
#pragma unroll
            for (int j = 0; j < 4; ++j) acc[mt][nt][j] = 0.0f;

    prefetch_chunk(Wt, 0, 0, sb, tid);

    for (int c = 0; c < NCH; ++c) {
        int buf = c & 1;
        if (c + 1 < NCH) { prefetch_chunk(Wt, c + 1, buf ^ 1, sb, tid); CP_WAIT(1); }
        else            { CP_WAIT(0); }
        __syncthreads();

        const uint4* Bc = (const uint4*)(smem + B_OFF + buf * 16384);

        uint32_t xi2[4];
        if (LAYER > 0) {
#pragma unroll
            for (int u = 0; u < 4; ++u) { float x = xr[u][c]; xi2[u] = packbf(x, x); }
        }

#pragma unroll
        for (int kp = 0; kp < 2; ++kp) {
            uint32_t afr0[2][4], afr1[2][4];
            gen_afr<LAYER>(2 * kp,     c, tq, xr, xb2, hr2, xi2, tab, afr0);
            gen_afr<LAYER>(2 * kp + 1, c, tq, xr, xb2, hr2, xi2, tab, afr1);
#pragma unroll
            for (int nt = 0; nt < 8; ++nt) {
                uint4 b = Bc[(kp * 16 + nt0 + nt) * 32 + lane];
                mma16816(acc[0][nt], afr0[0], b.x, b.y);
                mma16816(acc[1][nt], afr0[1], b.x, b.y);
                mma16816(acc[0][nt], afr1[0], b.z, b.w);
                mma16816(acc[1][nt], afr1[1], b.z, b.w);
            }
        }
        __syncthreads();
    }

    // ---- epilogue: relu, bf16x2 hidden writeback, weighted per-row sums ----
    float rsum[4] = {0.0f, 0.0f, 0.0f, 0.0f};
#pragma unroll
    for (int mt = 0; mt < 2; ++mt) {
        int r = m0 + mt * 16 + q;
#pragma unroll
        for (int nt = 0; nt < 8; ++nt) {
            int c0 = n0 + nt * 8 + tq * 2;
            float v0 = fmaxf(acc[mt][nt][0], 0.0f);
            float v1 = fmaxf(acc[mt][nt][1], 0.0f);
            float v2 = fmaxf(acc[mt][nt][2], 0.0f);
            float v3 = fmaxf(acc[mt][nt][3], 0.0f);
            if (LAYER == 2 || c0 >= 64) {
                int wi = (LAYER == 0) ? (c0 - 64) : (LAYER == 1 ? c0 : 128 + c0);
                float w0 = wf[wi], w1 = wf[wi + 1];
                rsum[mt * 2]     += v0 * w0 + v1 * w1;
                rsum[mt * 2 + 1] += v2 * w0 + v3 * w1;
            } else {  // hidden half (LAYER < 2, wn == 0), cols c0, c0+1 adjacent
                hsf2[r * H2S + (c0 >> 1)]       = packbf(v0, v1);
                hsf2[(r + 8) * H2S + (c0 >> 1)] = packbf(v2, v3);
            }
        }
    }
#pragma unroll
    for (int m = 1; m <= 2; m <<= 1)
#pragma unroll
        for (int t = 0; t < 4; ++t)
            rsum[t] += __shfl_xor_sync(0xffffffffu, rsum[t], m);
    if (tq == 0) {
        ra[(m0 + q) * 2 + wn]      = rsum[0];
        ra[(m0 + q + 8) * 2 + wn]  = rsum[1];
        ra[(m0 + q + 16) * 2 + wn] = rsum[2];
        ra[(m0 + q + 24) * 2 + wn] = rsum[3];
    }
    __syncthreads();

    if (tid < 8) {
        float s = 0.0f;
#pragma unroll
        for (int d = 0; d < 16; ++d)
            s += ra[(tid * 16 + d) * 2] + ra[(tid * 16 + d) * 2 + 1];
        score[tid] += s;
    }
    __syncthreads();
}

// ---------------- main kernel ----------------
__global__ __launch_bounds__(kNT, 2)
void cin_main(const float* __restrict__ nn_input, const float* __restrict__ w_nn,
              const float* __restrict__ b_nn, float* __restrict__ out) {
    extern __shared__ __align__(16) char smem[];
    uint32_t sb = smem_u32(smem);
    int tid = threadIdx.x;

    float*    x0f   = (float*)(smem + XF_OFF);
    uint32_t* x0b   = (uint32_t*)(smem + XB_OFF);
    float*    wf    = (float*)(smem + W_OFF);
    float*    score = (float*)(smem + S_OFF);
    int*      tabs  = (int*)(smem + T_OFF);

    int S0 = blockIdx.x * 8;
    for (int idx = tid; idx < 8 * 624; idx += kNT) {
        int s = idx / 624, rem = idx - s * 624;
        int i = rem >> 4, d = rem & 15;
        x0f[(s * 16 + d) * XS + i] = nn_input[(size_t)(S0 + s) * 624 + rem];
    }
    for (int idx = tid; idx < 128 * 3; idx += kNT) {          // pad cols 39..41 = 0
        int r = idx / 3, p = idx - 3 * r;
        x0f[r * XS + 39 + p] = 0.0f;
    }
    if (tid < 224) tabs[tid] = g_L0map[tid];
    wf[tid] = 1.0f + w_nn[tid];                               // tid < 256 always
    if (tid < 8) score[tid] = b_nn[0];
    __syncthreads();                                          // x0f complete

    // bf16x2 x0 copy for layer-0 j-pair loads (cols 0..39, col 39 pad = 0)
    for (int idx = tid; idx < 128 * 20; idx += kNT) {
        int r = idx / 20, m = idx - r * 20;
        x0b[r * XB2 + m] = packbf(x0f[r * XS + 2 * m], x0f[r * XS + 2 * m + 1]);
    }
    // visibility covered by first chunk's in-loop __syncthreads

    run_layer<0>(smem, sb, g_Wt0);
    run_layer<1>(smem, sb, g_Wt1);
    run_layer<2>(smem, sb, g_Wt2);

    if (tid < 8) out[S0 + tid] = score[tid];
}

// ---------------- launch ----------------
extern "C" void kernel_launch(void* const* d_in, const int* in_sizes, int n_in,
                              void* d_out, int out_size) {
    const float* nn   = (const float*)d_in[0];
    const float* f0   = (const float*)d_in[1];
    const float* f1   = (const float*)d_in[2];
    const float* f2   = (const float*)d_in[3];
    const float* w_nn = (const float*)d_in[4];
    const float* b_nn = (const float*)d_in[5];
    float* out = (float*)d_out;

    cudaFuncSetAttribute(cin_main, cudaFuncAttributeMaxDynamicSharedMemorySize, SMEM_ALLOC);

    uint2* wt0; cudaGetSymbolAddress((void**)&wt0, g_Wt0);
    uint2* wt1; cudaGetSymbolAddress((void**)&wt1, g_Wt1);
    uint2* wt2; cudaGetSymbolAddress((void**)&wt2, g_Wt2);

    cin_l0map<<<1, 32>>>();
    cin_wprep<<<(NCH0  * 2048 + 255) / 256, 256>>>(f0, wt0, 0, NCH0);
    cin_wprep<<<(NCH12 * 2048 + 255) / 256, 256>>>(f1, wt1, 1, NCH12);
    cin_wprep<<<(NCH12 * 2048 + 255) / 256, 256>>>(f2, wt2, 2, NCH12);
    cin_main<<<kNCTA, kNT, SMEM_ALLOC>>>(nn, w_nn, b_nn, out);
}